// round 11
// baseline (speedup 1.0000x reference)
#include <cuda_runtime.h>
#include <stdint.h>

// Problem constants
#define TT 2048
#define BB 128
#define KK 64
#define NTHREADS 768   // 24 warps: 0-1 = A/C; 2-23 = 3 rows each (66, 2 dummy)

// ---------------------------------------------------------------------------
// Threefry-2x32, 20 rounds, exactly as jax._src.prng.threefry2x32 (SHF rotate)
// ---------------------------------------------------------------------------
__device__ __forceinline__ uint2 tf2x32(uint32_t k0, uint32_t k1,
                                        uint32_t x0, uint32_t x1) {
    uint32_t ks2 = k0 ^ k1 ^ 0x1BD11BDAu;
    x0 += k0; x1 += k1;
#define TFR(r) { x0 += x1; x1 = __funnelshift_l(x1, x1, (r)); x1 ^= x0; }
    TFR(13) TFR(15) TFR(26) TFR(6)
    x0 += k1; x1 += ks2 + 1u;
    TFR(17) TFR(29) TFR(16) TFR(24)
    x0 += ks2; x1 += k0 + 2u;
    TFR(13) TFR(15) TFR(26) TFR(6)
    x0 += k0; x1 += k1 + 3u;
    TFR(17) TFR(29) TFR(16) TFR(24)
    x0 += k1; x1 += ks2 + 4u;
    TFR(13) TFR(15) TFR(26) TFR(6)
    x0 += ks2; x1 += k0 + 5u;
#undef TFR
    return make_uint2(x0, x1);
}

__device__ __forceinline__ float bits_to_u01(uint32_t bits) {
    return __uint_as_float((bits >> 9) | 0x3f800000u) - 1.0f;
}

#define TINYF 1.17549435082228751e-38f

// Fast polynomial -log(u) for u in (0,1). ~16 instr, NO MUFU, BRANCHLESS
// (range reduction via select, not if -- avoids BSSY/BSYNC per call).
// Relative error ~2e-7 uniformly (log1p form is exact-dominant near u=1).
__device__ __forceinline__ float neglog_poly(uint32_t bits) {
    float u = fmaxf(bits_to_u01(bits), TINYF);
    int   i = __float_as_int(u);
    int   e = (i >> 23) - 127;
    float m = __int_as_float((i & 0x007fffff) | 0x3f800000);  // [1,2)
    bool  c = m > 1.41421356237f;
    m = c ? m * 0.5f : m;            // FSEL, branchless
    e = c ? e + 1 : e;               // SEL
    float f = m - 1.0f;
    float z = f * f;
    float p =              7.0376836292e-2f;
    p = fmaf(p, f, -1.1514610310e-1f);
    p = fmaf(p, f,  1.1676998740e-1f);
    p = fmaf(p, f, -1.2420140846e-1f);
    p = fmaf(p, f,  1.4249322787e-1f);
    p = fmaf(p, f, -1.6668057665e-1f);
    p = fmaf(p, f,  2.0000714765e-1f);
    p = fmaf(p, f, -2.4999993993e-1f);
    p = fmaf(p, f,  3.3333331174e-1f);
    float y = (f * z) * p;
    float ef = (float)e;
    y = fmaf(ef, -2.12194440e-4f, y);   // ln2 low part
    y = fmaf(z, -0.5f, y);
    float r = f + y + ef * 0.693359375f;  // ln2 high part
    return -r;
}

// XLA/CHLO ErfInv32 polynomial (Giles) -- precise path (feeds state)
__device__ __forceinline__ float erfinv_xla(float x) {
    float w = -log1pf(-x * x);
    float p;
    if (w < 5.0f) {
        w = w - 2.5f;
        p = 2.81022636e-08f;
        p = fmaf(p, w, 3.43273939e-07f);
        p = fmaf(p, w, -3.5233877e-06f);
        p = fmaf(p, w, -4.39150654e-06f);
        p = fmaf(p, w, 0.00021858087f);
        p = fmaf(p, w, -0.00125372503f);
        p = fmaf(p, w, -0.00417768164f);
        p = fmaf(p, w, 0.246640727f);
        p = fmaf(p, w, 1.50140941f);
    } else {
        w = sqrtf(w) - 3.0f;
        p = -0.000200214257f;
        p = fmaf(p, w, 0.000100950558f);
        p = fmaf(p, w, 0.00134934322f);
        p = fmaf(p, w, -0.00367342844f);
        p = fmaf(p, w, 0.00573950773f);
        p = fmaf(p, w, -0.0076224613f);
        p = fmaf(p, w, 0.00943887047f);
        p = fmaf(p, w, 1.00167406f);
        p = fmaf(p, w, 2.83297682f);
    }
    return p * x;
}

// Exact reference gumbel (libdevice logf), used only on fallback rows.
__device__ __forceinline__ float gumbel_exact(uint32_t bits) {
    float u = bits_to_u01(bits);
    float v = fmaxf(u, TINYF);
    return -logf(-logf(v));
}

// ---------------------------------------------------------------------------
// Fill the 4 constant columns of pf_out once
// ---------------------------------------------------------------------------
__global__ void fill_const_kernel(const float* __restrict__ params,
                                  float* __restrict__ pf) {
    const float p0 = params[0], p1 = params[1], p2 = params[2], p3 = params[3];
    const size_t n = (size_t)TT * KK * BB;
    size_t idx = (size_t)blockIdx.x * blockDim.x + threadIdx.x;
    if (idx < n) {
        float* o = pf + idx * 5;
        o[0] = p0; o[1] = p1; o[2] = p2; o[3] = p3;
    }
}

// ---------------------------------------------------------------------------
// Persistent kernel: 1 CTA per batch element b.
//   warps 0-1 : phase A (eps/vol/weights) + phase C (resample/output)
//   warps 2-23: 3 categorical rows each, UNIFORM (66 rows; 64,65 = dummies
//               computed-and-discarded to keep the hot loop branch-free).
// Categorical: argmin of t = e * (1/q) via a single REDUX.MIN.U32 on keys
// (float bits truncated to 26 bits) | particle index, with exact-formula
// fallback for rows whose top-2 gap is within 1e-4 relative.
// ---------------------------------------------------------------------------
__global__ void __launch_bounds__(NTHREADS, 1)
garch_pf_kernel(const float* __restrict__ obs,     // (B, T, 2)
                const float* __restrict__ vol0,    // (K*B, 1)
                const float* __restrict__ params,  // (4,)
                float* __restrict__ out) {
    const int b    = blockIdx.x;
    const int tid  = threadIdx.x;
    const int lane = tid & 31;
    const int warp = tid >> 5;

    __shared__ uint2 skey[TT];     // per-step key_t
    __shared__ uint2 sckey[TT];    // fold_in(key_t, 1)
    __shared__ float r_s[TT];      // obs[b, t, 0]
    __shared__ float rinv_s[KK];   // 1/q
    __shared__ float q_s[KK];      // q (fallback + phase C)
    __shared__ float nv_s[KK], wn_s[KK];
    __shared__ float vol_s[KK], w_s[KK];
    __shared__ int   idx_s[KK];
    __shared__ float redm_s[2], reds_s[2];

    for (int t = tid; t < TT; t += NTHREADS) {
        uint2 kt = tf2x32(0u, 42u, 0u, (uint32_t)t);
        skey[t]  = kt;
        sckey[t] = tf2x32(kt.x, kt.y, 0u, 1u);
        r_s[t]   = obs[((size_t)b * TT + t) * 2];
    }
    if (warp < 2) {
        const int pa = warp * 32 + lane;
        vol_s[pa] = vol0[pa * BB + b];
        w_s[pa]   = 1.0f / 64.0f;
    }
    const float c0 = params[0], q1 = params[1], q2 = params[2], r1 = params[3];
    const float r1e = 0.001f * r1;
    __syncthreads();

    float* __restrict__ y_out = out;                    // (T, B, 1)
    float* __restrict__ pf    = out + (size_t)TT * BB;  // (T, K*B, 5)

    const float MINVAL_N = -0.99999994039535522f;
    const float SQRT2    = 1.41421356237309515f;
    const float LOG2PI   = 1.83787706640934534f;
    const float ALPHA_F  = 0.3f;
    const float UNIFW    = (float)((1.0 - 0.3) / 64.0);
    const float MARGIN   = 1.0001f;   // 1e-4 relative fallback margin

    // Uniform B-warp row assignment: warp w (2..23) owns rows w2*3..w2*3+2.
    // Rows 64,65 (warp 23) are dummies: computed, never stored.
    const int w2   = warp - 2;
    const int row0 = w2 * 3;

    float    e0v[3], e1v[3];                 // fast -log(u) per row
    uint32_t b0v[3], b1v[3];                 // raw bits (fallback recompute)

    for (int t = 0; t < TT; t++) {
        if (warp < 2) {
            // ---------------- Phase A: 1 particle/lane across warps 0-1 ----
            const uint2 kt = skey[t];
            const float r    = r_s[t];
            const float rr   = r * r;
            const float q2rr = (q2 * r) * r;
            const int pa = warp * 32 + lane;

            uint2 bl = tf2x32(kt.x, kt.y, 0u, (uint32_t)(pa * BB + b));
            float u  = bits_to_u01(bl.x ^ bl.y);
            float v  = fmaxf(MINVAL_N, u * 2.0f + MINVAL_N);
            float eps = SQRT2 * erfinv_xla(v);
            float x   = ((c0 + q1 * vol_s[pa]) + q2rr) + r1e * eps;
            float nvv = fabsf(x) + 1e-8f;
            float ll  = -0.5f * ((rr / nvv + logf(nvv)) + LOG2PI);
            float lw  = logf(w_s[pa] + 1e-12f) + ll;

            // logsumexp over 64 across the two warps
            float m = lw;
#pragma unroll
            for (int o = 16; o; o >>= 1)
                m = fmaxf(m, __shfl_xor_sync(0xffffffffu, m, o));
            if (lane == 0) redm_s[warp] = m;
            asm volatile("bar.sync 1, 64;" ::: "memory");
            float mm = fmaxf(redm_s[0], redm_s[1]);
            float s  = expf(lw - mm);
#pragma unroll
            for (int o = 16; o; o >>= 1)
                s += __shfl_xor_sync(0xffffffffu, s, o);
            if (lane == 0) reds_s[warp] = s;
            asm volatile("bar.sync 1, 64;" ::: "memory");
            float lse = logf(reds_s[0] + reds_s[1]) + mm;

            float wn = expf(lw - lse);
            float q  = ALPHA_F * wn + UNIFW;
            nv_s[pa]   = nvv;
            wn_s[pa]   = wn;
            q_s[pa]    = q;
            rinv_s[pa] = 1.0f / q;
        } else {
            // ---------------- Phase B1: state-independent exp draws --------
            // Uniform 3 rows/warp, no guards: 6 independent threefry chains
            // interleave freely for ILP.
            const uint2 ck = sckey[t];
            const uint32_t bb64 = (uint32_t)(b * KK);
#pragma unroll
            for (int ii = 0; ii < 3; ii++) {
                const uint32_t i  = (uint32_t)(row0 + ii);
                const uint32_t cb = i * 8192u + bb64;   // i*B*K + b*K
                uint2 ga = tf2x32(ck.x, ck.y, 0u, cb + (uint32_t)lane);
                uint2 gb = tf2x32(ck.x, ck.y, 0u, cb + (uint32_t)lane + 32u);
                b0v[ii] = ga.x ^ ga.y;
                b1v[ii] = gb.x ^ gb.y;
                e0v[ii] = neglog_poly(b0v[ii]);
                e1v[ii] = neglog_poly(b1v[ii]);
            }
        }
        __syncthreads();   // rinv/q published; B1 done

        if (warp >= 2) {
            // -------- Phase B2: REDUX argmin of e/q keys, exact fallback ---
            const float ra = rinv_s[lane];
            const float rb = rinv_s[lane + 32];
#pragma unroll
            for (int ii = 0; ii < 3; ii++) {
                const int row = row0 + ii;
                float t0 = e0v[ii] * ra;       // positive -> uint-monotone
                float t1 = e1v[ii] * rb;
                // key = truncated float bits | index (tie -> lowest index)
                uint32_t k0 = (__float_as_uint(t0) & 0xFFFFFFC0u) | (uint32_t)lane;
                uint32_t k1 = (__float_as_uint(t1) & 0xFFFFFFC0u) | (uint32_t)(lane + 32);
                uint32_t km = k0 < k1 ? k0 : k1;
                uint32_t wk = __reduce_min_sync(0xffffffffu, km);
                int bj = (int)(wk & 63u);
                float thr = __uint_as_float(wk & 0xFFFFFFC0u) * MARGIN;
                // near-tie detection (excluding the winner itself)
                bool nr = ((lane      != bj) && (t0 <= thr)) ||
                          ((lane + 32 != bj) && (t1 <= thr));
                if (row < KK) {   // warp-uniform: dummy rows skip entirely
                    if (__ballot_sync(0xffffffffu, nr)) {
                        // exact reference formula: argmax(gumbel + log q)
                        float s0 = gumbel_exact(b0v[ii]) + logf(q_s[lane]);
                        float s1 = gumbel_exact(b1v[ii]) + logf(q_s[lane + 32]);
                        float fb; int fj;
                        if (s1 > s0) { fb = s1; fj = lane + 32; }
                        else         { fb = s0; fj = lane; }
#pragma unroll
                        for (int o = 16; o; o >>= 1) {
                            float ov = __shfl_xor_sync(0xffffffffu, fb, o);
                            int   oj = __shfl_xor_sync(0xffffffffu, fj, o);
                            if (ov > fb || (ov == fb && oj < fj)) { fb = ov; fj = oj; }
                        }
                        bj = fj;
                    }
                    if (lane == 0) idx_s[row] = bj;
                }
            }
        }
        __syncthreads();   // idx published; B warps free-run into B1(t+1)

        if (warp < 2) {
            // ---------------- Phase C: resample, normalize, outputs --------
            if (warp == 0) {
                const int ia = idx_s[lane], ib = idx_s[lane + 32];
                float vra = nv_s[ia], vrb = nv_s[ib];
                float wra = wn_s[ia] / q_s[ia];
                float wrb = wn_s[ib] / q_s[ib];
                float ssum = wra + wrb;
#pragma unroll
                for (int o = 16; o; o >>= 1)
                    ssum += __shfl_xor_sync(0xffffffffu, ssum, o);
                wra /= ssum; wrb /= ssum;
                vol_s[lane]      = vra; vol_s[lane + 32] = vrb;
                w_s[lane]        = wra; w_s[lane + 32]   = wrb;
                float y = vra * wra + vrb * wrb;
#pragma unroll
                for (int o = 16; o; o >>= 1)
                    y += __shfl_xor_sync(0xffffffffu, y, o);
                if (lane == 0) y_out[(size_t)t * BB + b] = y;
                pf[((size_t)t * (KK * BB) + (size_t)lane * BB + b) * 5 + 4] = vra;
                pf[((size_t)t * (KK * BB) + (size_t)(lane + 32) * BB + b) * 5 + 4] = vrb;
            }
            // warp1 waits for C's state writes before A(t+1)
            asm volatile("bar.sync 1, 64;" ::: "memory");
        }
    }
}

// ---------------------------------------------------------------------------
extern "C" void kernel_launch(void* const* d_in, const int* in_sizes, int n_in,
                              void* d_out, int out_size) {
    const float* obs    = (const float*)d_in[0];  // (128, 2048, 2)
    const float* vol0   = (const float*)d_in[1];  // (8192, 1)
    const float* params = (const float*)d_in[2];  // (4,)
    float* out = (float*)d_out;

    float* pf = out + (size_t)TT * BB;
    fill_const_kernel<<<65536, 256>>>(params, pf);
    garch_pf_kernel<<<BB, NTHREADS>>>(obs, vol0, params, out);
}

// round 12
// speedup vs baseline: 1.0207x; 1.0207x over previous
#include <cuda_runtime.h>
#include <stdint.h>

// Problem constants
#define TT 2048
#define BB 128
#define KK 64
#define NTHREADS 768   // 24 warps: 0-1 = A/C; 2-21 = 3 rows; 22-23 = 2 rows

// Named producer/consumer barriers (id 0 reserved for __syncthreads, 1 for
// the warp0/1 pair barrier).
#define BAR_RINV 2   // A-warps arrive after publishing rinv/q/nv/wn; B-warps sync
#define BAR_IDX  3   // B-warps arrive after publishing idx; warps 0-1 sync
#define BAR_CNT  768

__device__ __forceinline__ void bar_arrive(int id) {
    asm volatile("bar.arrive %0, %1;" :: "r"(id), "r"(BAR_CNT) : "memory");
}
__device__ __forceinline__ void bar_wait(int id) {
    asm volatile("bar.sync %0, %1;" :: "r"(id), "r"(BAR_CNT) : "memory");
}

// ---------------------------------------------------------------------------
// Threefry-2x32, 20 rounds, exactly as jax._src.prng.threefry2x32 (SHF rotate)
// ---------------------------------------------------------------------------
__device__ __forceinline__ uint2 tf2x32(uint32_t k0, uint32_t k1,
                                        uint32_t x0, uint32_t x1) {
    uint32_t ks2 = k0 ^ k1 ^ 0x1BD11BDAu;
    x0 += k0; x1 += k1;
#define TFR(r) { x0 += x1; x1 = __funnelshift_l(x1, x1, (r)); x1 ^= x0; }
    TFR(13) TFR(15) TFR(26) TFR(6)
    x0 += k1; x1 += ks2 + 1u;
    TFR(17) TFR(29) TFR(16) TFR(24)
    x0 += ks2; x1 += k0 + 2u;
    TFR(13) TFR(15) TFR(26) TFR(6)
    x0 += k0; x1 += k1 + 3u;
    TFR(17) TFR(29) TFR(16) TFR(24)
    x0 += k1; x1 += ks2 + 4u;
    TFR(13) TFR(15) TFR(26) TFR(6)
    x0 += ks2; x1 += k0 + 5u;
#undef TFR
    return make_uint2(x0, x1);
}

__device__ __forceinline__ float bits_to_u01(uint32_t bits) {
    return __uint_as_float((bits >> 9) | 0x3f800000u) - 1.0f;
}

#define TINYF 1.17549435082228751e-38f

// Fast polynomial -log(u) for u in (0,1). ~16 instr, NO MUFU.
// Relative error ~2e-7 uniformly (log1p form is exact-dominant near u=1).
__device__ __forceinline__ float neglog_poly(uint32_t bits) {
    float u = fmaxf(bits_to_u01(bits), TINYF);
    int   i = __float_as_int(u);
    int   e = (i >> 23) - 127;
    float m = __int_as_float((i & 0x007fffff) | 0x3f800000);  // [1,2)
    if (m > 1.41421356237f) { m *= 0.5f; e += 1; }            // [0.707,1.414]
    float f = m - 1.0f;
    float z = f * f;
    float p =              7.0376836292e-2f;
    p = fmaf(p, f, -1.1514610310e-1f);
    p = fmaf(p, f,  1.1676998740e-1f);
    p = fmaf(p, f, -1.2420140846e-1f);
    p = fmaf(p, f,  1.4249322787e-1f);
    p = fmaf(p, f, -1.6668057665e-1f);
    p = fmaf(p, f,  2.0000714765e-1f);
    p = fmaf(p, f, -2.4999993993e-1f);
    p = fmaf(p, f,  3.3333331174e-1f);
    float y = (f * z) * p;
    float ef = (float)e;
    y = fmaf(ef, -2.12194440e-4f, y);   // ln2 low part
    y = fmaf(z, -0.5f, y);
    float r = f + y + ef * 0.693359375f;  // ln2 high part
    return -r;
}

// XLA/CHLO ErfInv32 polynomial (Giles) -- precise path (feeds state)
__device__ __forceinline__ float erfinv_xla(float x) {
    float w = -log1pf(-x * x);
    float p;
    if (w < 5.0f) {
        w = w - 2.5f;
        p = 2.81022636e-08f;
        p = fmaf(p, w, 3.43273939e-07f);
        p = fmaf(p, w, -3.5233877e-06f);
        p = fmaf(p, w, -4.39150654e-06f);
        p = fmaf(p, w, 0.00021858087f);
        p = fmaf(p, w, -0.00125372503f);
        p = fmaf(p, w, -0.00417768164f);
        p = fmaf(p, w, 0.246640727f);
        p = fmaf(p, w, 1.50140941f);
    } else {
        w = sqrtf(w) - 3.0f;
        p = -0.000200214257f;
        p = fmaf(p, w, 0.000100950558f);
        p = fmaf(p, w, 0.00134934322f);
        p = fmaf(p, w, -0.00367342844f);
        p = fmaf(p, w, 0.00573950773f);
        p = fmaf(p, w, -0.0076224613f);
        p = fmaf(p, w, 0.00943887047f);
        p = fmaf(p, w, 1.00167406f);
        p = fmaf(p, w, 2.83297682f);
    }
    return p * x;
}

// Exact reference gumbel (libdevice logf), used only on fallback rows.
__device__ __forceinline__ float gumbel_exact(uint32_t bits) {
    float u = bits_to_u01(bits);
    float v = fmaxf(u, TINYF);
    return -logf(-logf(v));
}

// ---------------------------------------------------------------------------
// Fill the 4 constant columns of pf_out once
// ---------------------------------------------------------------------------
__global__ void fill_const_kernel(const float* __restrict__ params,
                                  float* __restrict__ pf) {
    const float p0 = params[0], p1 = params[1], p2 = params[2], p3 = params[3];
    const size_t n = (size_t)TT * KK * BB;
    size_t idx = (size_t)blockIdx.x * blockDim.x + threadIdx.x;
    if (idx < n) {
        float* o = pf + idx * 5;
        o[0] = p0; o[1] = p1; o[2] = p2; o[3] = p3;
    }
}

// ---------------------------------------------------------------------------
// Persistent kernel: 1 CTA per batch element b. r10 layout + producer/consumer
// named barriers (arrive/wait split) so B-warps never wait on each other:
//   A-warps:  A(0); arrive(RINV)
//             loop t: wait(IDX); C(t); bar1; A(t+1); arrive(RINV)
//   B-warps:  B1(0)
//             loop t: wait(RINV); B2(t); arrive(IDX); B1(t+1)
// ---------------------------------------------------------------------------
__global__ void __launch_bounds__(NTHREADS, 1)
garch_pf_kernel(const float* __restrict__ obs,     // (B, T, 2)
                const float* __restrict__ vol0,    // (K*B, 1)
                const float* __restrict__ params,  // (4,)
                float* __restrict__ out) {
    const int b    = blockIdx.x;
    const int tid  = threadIdx.x;
    const int lane = tid & 31;
    const int warp = tid >> 5;

    __shared__ uint2 skey[TT];     // per-step key_t
    __shared__ uint2 sckey[TT];    // fold_in(key_t, 1)
    __shared__ float r_s[TT];      // obs[b, t, 0]
    __shared__ float rinv_s[KK];   // 1/q
    __shared__ float q_s[KK];      // q (fallback + phase C)
    __shared__ float nv_s[KK], wn_s[KK];
    __shared__ float vol_s[KK], w_s[KK];
    __shared__ int   idx_s[KK];
    __shared__ float redm_s[2], reds_s[2];

    for (int t = tid; t < TT; t += NTHREADS) {
        uint2 kt = tf2x32(0u, 42u, 0u, (uint32_t)t);
        skey[t]  = kt;
        sckey[t] = tf2x32(kt.x, kt.y, 0u, 1u);
        r_s[t]   = obs[((size_t)b * TT + t) * 2];
    }
    if (warp < 2) {
        const int pa = warp * 32 + lane;
        vol_s[pa] = vol0[pa * BB + b];
        w_s[pa]   = 1.0f / 64.0f;
    }
    const float c0 = params[0], q1 = params[1], q2 = params[2], r1 = params[3];
    const float r1e = 0.001f * r1;
    __syncthreads();

    float* __restrict__ y_out = out;                    // (T, B, 1)
    float* __restrict__ pf    = out + (size_t)TT * BB;  // (T, K*B, 5)

    const float MINVAL_N = -0.99999994039535522f;
    const float SQRT2    = 1.41421356237309515f;
    const float LOG2PI   = 1.83787706640934534f;
    const float ALPHA_F  = 0.3f;
    const float UNIFW    = (float)((1.0 - 0.3) / 64.0);
    const float MARGIN   = 1.0001f;   // 1e-4 relative fallback margin

    if (warp < 2) {
        // ================= A/C warps ========================================
        const int pa = warp * 32 + lane;
        for (int t = 0; t < TT; t++) {
            // ---- Phase A(t): uses state from C(t-1) (or init) --------------
            {
                const uint2 kt = skey[t];
                const float r    = r_s[t];
                const float rr   = r * r;
                const float q2rr = (q2 * r) * r;

                uint2 bl = tf2x32(kt.x, kt.y, 0u, (uint32_t)(pa * BB + b));
                float u  = bits_to_u01(bl.x ^ bl.y);
                float v  = fmaxf(MINVAL_N, u * 2.0f + MINVAL_N);
                float eps = SQRT2 * erfinv_xla(v);
                float x   = ((c0 + q1 * vol_s[pa]) + q2rr) + r1e * eps;
                float nvv = fabsf(x) + 1e-8f;
                float ll  = -0.5f * ((rr / nvv + logf(nvv)) + LOG2PI);
                float lw  = logf(w_s[pa] + 1e-12f) + ll;

                // logsumexp over 64 across the two warps
                float m = lw;
#pragma unroll
                for (int o = 16; o; o >>= 1)
                    m = fmaxf(m, __shfl_xor_sync(0xffffffffu, m, o));
                if (lane == 0) redm_s[warp] = m;
                asm volatile("bar.sync 1, 64;" ::: "memory");
                float mm = fmaxf(redm_s[0], redm_s[1]);
                float s  = expf(lw - mm);
#pragma unroll
                for (int o = 16; o; o >>= 1)
                    s += __shfl_xor_sync(0xffffffffu, s, o);
                if (lane == 0) reds_s[warp] = s;
                asm volatile("bar.sync 1, 64;" ::: "memory");
                float lse = logf(reds_s[0] + reds_s[1]) + mm;

                float wn = expf(lw - lse);
                float q  = ALPHA_F * wn + UNIFW;
                nv_s[pa]   = nvv;
                wn_s[pa]   = wn;
                q_s[pa]    = q;
                rinv_s[pa] = 1.0f / q;
            }
            bar_arrive(BAR_RINV);       // rinv(t) published for B-warps

            // ---- wait for idx(t), then C(t) --------------------------------
            bar_wait(BAR_IDX);
            if (warp == 0) {
                const int ia = idx_s[lane], ib = idx_s[lane + 32];
                float vra = nv_s[ia], vrb = nv_s[ib];
                float wra = wn_s[ia] / q_s[ia];
                float wrb = wn_s[ib] / q_s[ib];
                float ssum = wra + wrb;
#pragma unroll
                for (int o = 16; o; o >>= 1)
                    ssum += __shfl_xor_sync(0xffffffffu, ssum, o);
                wra /= ssum; wrb /= ssum;
                vol_s[lane]      = vra; vol_s[lane + 32] = vrb;
                w_s[lane]        = wra; w_s[lane + 32]   = wrb;
                float y = vra * wra + vrb * wrb;
#pragma unroll
                for (int o = 16; o; o >>= 1)
                    y += __shfl_xor_sync(0xffffffffu, y, o);
                if (lane == 0) y_out[(size_t)t * BB + b] = y;
                pf[((size_t)t * (KK * BB) + (size_t)lane * BB + b) * 5 + 4] = vra;
                pf[((size_t)t * (KK * BB) + (size_t)(lane + 32) * BB + b) * 5 + 4] = vrb;
            }
            // order C's state writes before A(t+1) on both warps 0,1
            asm volatile("bar.sync 1, 64;" ::: "memory");
        }
    } else {
        // ================= B warps (categorical rows) =======================
        // Row assignment (r10-verified): w2 = warp-2 in 0..21.
        const int w2    = warp - 2;
        const int nrows = (w2 < 20) ? 3 : 2;
        const int row0  = (w2 < 20) ? w2 * 3 : 60 + (w2 - 20) * 2;

        float    e0v[3], e1v[3];
        uint32_t b0v[3], b1v[3];

        // ---- B1(0) prologue ------------------------------------------------
        {
            const uint2 ck = sckey[0];
            const uint32_t bb64 = (uint32_t)(b * KK);
#pragma unroll
            for (int ii = 0; ii < 3; ii++) {
                if (ii < nrows) {
                    const uint32_t i  = (uint32_t)(row0 + ii);
                    const uint32_t cb = i * 8192u + bb64;
                    uint2 ga = tf2x32(ck.x, ck.y, 0u, cb + (uint32_t)lane);
                    uint2 gb = tf2x32(ck.x, ck.y, 0u, cb + (uint32_t)lane + 32u);
                    b0v[ii] = ga.x ^ ga.y;
                    b1v[ii] = gb.x ^ gb.y;
                    e0v[ii] = neglog_poly(b0v[ii]);
                    e1v[ii] = neglog_poly(b1v[ii]);
                }
            }
        }

        for (int t = 0; t < TT; t++) {
            // ---- wait for rinv(t), then B2(t) -------------------------------
            bar_wait(BAR_RINV);
            {
                const float ra = rinv_s[lane];
                const float rb = rinv_s[lane + 32];
#pragma unroll
                for (int ii = 0; ii < 3; ii++) {
                    if (ii < nrows) {
                        float t0 = e0v[ii] * ra;   // positive -> uint-monotone
                        float t1 = e1v[ii] * rb;
                        uint32_t k0 = (__float_as_uint(t0) & 0xFFFFFFC0u) | (uint32_t)lane;
                        uint32_t k1 = (__float_as_uint(t1) & 0xFFFFFFC0u) | (uint32_t)(lane + 32);
                        uint32_t km = k0 < k1 ? k0 : k1;
                        uint32_t wk = __reduce_min_sync(0xffffffffu, km);
                        int bj = (int)(wk & 63u);
                        float thr = __uint_as_float(wk & 0xFFFFFFC0u) * MARGIN;
                        bool nr = ((lane      != bj) && (t0 <= thr)) ||
                                  ((lane + 32 != bj) && (t1 <= thr));
                        if (__ballot_sync(0xffffffffu, nr)) {
                            // exact reference formula: argmax(gumbel + log q)
                            float s0 = gumbel_exact(b0v[ii]) + logf(q_s[lane]);
                            float s1 = gumbel_exact(b1v[ii]) + logf(q_s[lane + 32]);
                            float fb; int fj;
                            if (s1 > s0) { fb = s1; fj = lane + 32; }
                            else         { fb = s0; fj = lane; }
#pragma unroll
                            for (int o = 16; o; o >>= 1) {
                                float ov = __shfl_xor_sync(0xffffffffu, fb, o);
                                int   oj = __shfl_xor_sync(0xffffffffu, fj, o);
                                if (ov > fb || (ov == fb && oj < fj)) { fb = ov; fj = oj; }
                            }
                            bj = fj;
                        }
                        if (lane == 0) idx_s[row0 + ii] = bj;
                    }
                }
            }
            bar_arrive(BAR_IDX);        // idx(t) published; flow on freely

            // ---- B1(t+1): state-independent, no waiting ---------------------
            if (t + 1 < TT) {
                const uint2 ck = sckey[t + 1];
                const uint32_t bb64 = (uint32_t)(b * KK);
#pragma unroll
                for (int ii = 0; ii < 3; ii++) {
                    if (ii < nrows) {
                        const uint32_t i  = (uint32_t)(row0 + ii);
                        const uint32_t cb = i * 8192u + bb64;
                        uint2 ga = tf2x32(ck.x, ck.y, 0u, cb + (uint32_t)lane);
                        uint2 gb = tf2x32(ck.x, ck.y, 0u, cb + (uint32_t)lane + 32u);
                        b0v[ii] = ga.x ^ ga.y;
                        b1v[ii] = gb.x ^ gb.y;
                        e0v[ii] = neglog_poly(b0v[ii]);
                        e1v[ii] = neglog_poly(b1v[ii]);
                    }
                }
            }
        }
    }
}

// ---------------------------------------------------------------------------
extern "C" void kernel_launch(void* const* d_in, const int* in_sizes, int n_in,
                              void* d_out, int out_size) {
    const float* obs    = (const float*)d_in[0];  // (128, 2048, 2)
    const float* vol0   = (const float*)d_in[1];  // (8192, 1)
    const float* params = (const float*)d_in[2];  // (4,)
    float* out = (float*)d_out;

    float* pf = out + (size_t)TT * BB;
    fill_const_kernel<<<65536, 256>>>(params, pf);
    garch_pf_kernel<<<BB, NTHREADS>>>(obs, vol0, params, out);
}

// round 14
// speedup vs baseline: 1.0458x; 1.0246x over previous
#include <cuda_runtime.h>
#include <stdint.h>

// Problem constants
#define TT 2048
#define BB 128
#define KK 64
#define NTHREADS 768   // 24 warps: 0-1 = A/C; 2-21 = 3 rows; 22-23 = 2 rows

// ---------------------------------------------------------------------------
// mbarrier helpers (shared-memory, cta scope)
// ---------------------------------------------------------------------------
__device__ __forceinline__ void mbar_init(uint32_t addr, uint32_t count) {
    asm volatile("mbarrier.init.shared.b64 [%0], %1;"
                 :: "r"(addr), "r"(count) : "memory");
}
__device__ __forceinline__ void mbar_arrive(uint32_t addr) {
    asm volatile("mbarrier.arrive.release.cta.shared::cta.b64 _, [%0];"
                 :: "r"(addr) : "memory");
}
__device__ __forceinline__ void mbar_wait(uint32_t addr, uint32_t parity) {
    asm volatile(
        "{\n\t"
        ".reg .pred P;\n"
        "WL_%=:\n\t"
        "mbarrier.try_wait.parity.acquire.cta.shared::cta.b64 P, [%0], %1, 0x989680;\n\t"
        "@P bra.uni WD_%=;\n\t"
        "bra.uni WL_%=;\n"
        "WD_%=:\n\t"
        "}"
        :: "r"(addr), "r"(parity) : "memory");
}

// ---------------------------------------------------------------------------
// Threefry-2x32, 20 rounds, exactly as jax._src.prng.threefry2x32 (SHF rotate)
// ---------------------------------------------------------------------------
__device__ __forceinline__ uint2 tf2x32(uint32_t k0, uint32_t k1,
                                        uint32_t x0, uint32_t x1) {
    uint32_t ks2 = k0 ^ k1 ^ 0x1BD11BDAu;
    x0 += k0; x1 += k1;
#define TFR(r) { x0 += x1; x1 = __funnelshift_l(x1, x1, (r)); x1 ^= x0; }
    TFR(13) TFR(15) TFR(26) TFR(6)
    x0 += k1; x1 += ks2 + 1u;
    TFR(17) TFR(29) TFR(16) TFR(24)
    x0 += ks2; x1 += k0 + 2u;
    TFR(13) TFR(15) TFR(26) TFR(6)
    x0 += k0; x1 += k1 + 3u;
    TFR(17) TFR(29) TFR(16) TFR(24)
    x0 += k1; x1 += ks2 + 4u;
    TFR(13) TFR(15) TFR(26) TFR(6)
    x0 += ks2; x1 += k0 + 5u;
#undef TFR
    return make_uint2(x0, x1);
}

__device__ __forceinline__ float bits_to_u01(uint32_t bits) {
    return __uint_as_float((bits >> 9) | 0x3f800000u) - 1.0f;
}

#define TINYF 1.17549435082228751e-38f

// Fast polynomial -log(u) for u in (0,1). ~16 instr, NO MUFU.
__device__ __forceinline__ float neglog_poly(uint32_t bits) {
    float u = fmaxf(bits_to_u01(bits), TINYF);
    int   i = __float_as_int(u);
    int   e = (i >> 23) - 127;
    float m = __int_as_float((i & 0x007fffff) | 0x3f800000);  // [1,2)
    if (m > 1.41421356237f) { m *= 0.5f; e += 1; }            // [0.707,1.414]
    float f = m - 1.0f;
    float z = f * f;
    float p =              7.0376836292e-2f;
    p = fmaf(p, f, -1.1514610310e-1f);
    p = fmaf(p, f,  1.1676998740e-1f);
    p = fmaf(p, f, -1.2420140846e-1f);
    p = fmaf(p, f,  1.4249322787e-1f);
    p = fmaf(p, f, -1.6668057665e-1f);
    p = fmaf(p, f,  2.0000714765e-1f);
    p = fmaf(p, f, -2.4999993993e-1f);
    p = fmaf(p, f,  3.3333331174e-1f);
    float y = (f * z) * p;
    float ef = (float)e;
    y = fmaf(ef, -2.12194440e-4f, y);   // ln2 low part
    y = fmaf(z, -0.5f, y);
    float r = f + y + ef * 0.693359375f;  // ln2 high part
    return -r;
}

// XLA/CHLO ErfInv32 polynomial (Giles) -- precise path (feeds state)
__device__ __forceinline__ float erfinv_xla(float x) {
    float w = -log1pf(-x * x);
    float p;
    if (w < 5.0f) {
        w = w - 2.5f;
        p = 2.81022636e-08f;
        p = fmaf(p, w, 3.43273939e-07f);
        p = fmaf(p, w, -3.5233877e-06f);
        p = fmaf(p, w, -4.39150654e-06f);
        p = fmaf(p, w, 0.00021858087f);
        p = fmaf(p, w, -0.00125372503f);
        p = fmaf(p, w, -0.00417768164f);
        p = fmaf(p, w, 0.246640727f);
        p = fmaf(p, w, 1.50140941f);
    } else {
        w = sqrtf(w) - 3.0f;
        p = -0.000200214257f;
        p = fmaf(p, w, 0.000100950558f);
        p = fmaf(p, w, 0.00134934322f);
        p = fmaf(p, w, -0.00367342844f);
        p = fmaf(p, w, 0.00573950773f);
        p = fmaf(p, w, -0.0076224613f);
        p = fmaf(p, w, 0.00943887047f);
        p = fmaf(p, w, 1.00167406f);
        p = fmaf(p, w, 2.83297682f);
    }
    return p * x;
}

// Exact reference gumbel (libdevice logf), used only on fallback rows.
__device__ __forceinline__ float gumbel_exact(uint32_t bits) {
    float u = bits_to_u01(bits);
    float v = fmaxf(u, TINYF);
    return -logf(-logf(v));
}

// ---------------------------------------------------------------------------
// Fill the 4 constant columns of pf_out once
// ---------------------------------------------------------------------------
__global__ void fill_const_kernel(const float* __restrict__ params,
                                  float* __restrict__ pf) {
    const float p0 = params[0], p1 = params[1], p2 = params[2], p3 = params[3];
    const size_t n = (size_t)TT * KK * BB;
    size_t idx = (size_t)blockIdx.x * blockDim.x + threadIdx.x;
    if (idx < n) {
        float* o = pf + idx * 5;
        o[0] = p0; o[1] = p1; o[2] = p2; o[3] = p3;
    }
}

// ---------------------------------------------------------------------------
// Persistent kernel: 1 CTA per batch element b. r10 layout, block-wide
// __syncthreads replaced by pairwise mbarriers so B-warps never wait on
// each other:
//   A-warps:  loop t: A(t); arrive(RINV); [w0: stores(t-1); wait(IDX); C(t)];
//             bar1
//   B-warps:  loop t: B1(t); wait(RINV,t); B2(t); arrive(IDX)  (free-running)
// ---------------------------------------------------------------------------
__global__ void __launch_bounds__(NTHREADS, 1)
garch_pf_kernel(const float* __restrict__ obs,     // (B, T, 2)
                const float* __restrict__ vol0,    // (K*B, 1)
                const float* __restrict__ params,  // (4,)
                float* __restrict__ out) {
    const int b    = blockIdx.x;
    const int tid  = threadIdx.x;
    const int lane = tid & 31;
    const int warp = tid >> 5;

    __shared__ uint2 skey[TT];     // per-step key_t
    __shared__ uint2 sckey[TT];    // fold_in(key_t, 1)
    __shared__ float r_s[TT];      // obs[b, t, 0]
    __shared__ float rinv_s[KK];   // 1/q
    __shared__ float q_s[KK];      // q (fallback + phase C)
    __shared__ float nv_s[KK], wn_s[KK];
    __shared__ float vol_s[KK], w_s[KK];
    __shared__ int   idx_s[KK];
    __shared__ float redm_s[2], reds_s[2];
    __shared__ alignas(8) uint64_t mb_rinv, mb_idx;

    const uint32_t a_rinv = (uint32_t)__cvta_generic_to_shared(&mb_rinv);
    const uint32_t a_idx  = (uint32_t)__cvta_generic_to_shared(&mb_idx);

    if (tid == 0) {
        mbar_init(a_rinv, 64);    // all lanes of warps 0-1 arrive
        mbar_init(a_idx, 704);    // all lanes of 22 B-warps arrive
    }
    for (int t = tid; t < TT; t += NTHREADS) {
        uint2 kt = tf2x32(0u, 42u, 0u, (uint32_t)t);
        skey[t]  = kt;
        sckey[t] = tf2x32(kt.x, kt.y, 0u, 1u);
        r_s[t]   = obs[((size_t)b * TT + t) * 2];
    }
    if (warp < 2) {
        const int pa = warp * 32 + lane;
        vol_s[pa] = vol0[pa * BB + b];
        w_s[pa]   = 1.0f / 64.0f;
    }
    const float c0 = params[0], q1 = params[1], q2 = params[2], r1 = params[3];
    const float r1e = 0.001f * r1;
    __syncthreads();

    float* __restrict__ y_out = out;                    // (T, B, 1)
    float* __restrict__ pf    = out + (size_t)TT * BB;  // (T, K*B, 5)

    const float MINVAL_N = -0.99999994039535522f;
    const float SQRT2    = 1.41421356237309515f;
    const float LOG2PI   = 1.83787706640934534f;
    const float ALPHA_F  = 0.3f;
    const float UNIFW    = (float)((1.0 - 0.3) / 64.0);
    const float MARGIN   = 1.0001f;   // 1e-4 relative fallback margin

    if (warp < 2) {
        // ================= A/C warps ========================================
        const int pa = warp * 32 + lane;
        float svra = 0.f, svrb = 0.f, spy = 0.f;   // step t-1 outputs (w0)

        for (int t = 0; t < TT; t++) {
            // ---- Phase A(t): produce rinv/q/nv/wn ---------------------------
            {
                const uint2 kt = skey[t];
                const float r    = r_s[t];
                const float rr   = r * r;
                const float q2rr = (q2 * r) * r;

                uint2 bl = tf2x32(kt.x, kt.y, 0u, (uint32_t)(pa * BB + b));
                float u  = bits_to_u01(bl.x ^ bl.y);
                float v  = fmaxf(MINVAL_N, u * 2.0f + MINVAL_N);
                float eps = SQRT2 * erfinv_xla(v);
                float x   = ((c0 + q1 * vol_s[pa]) + q2rr) + r1e * eps;
                float nvv = fabsf(x) + 1e-8f;
                float ll  = -0.5f * ((rr / nvv + logf(nvv)) + LOG2PI);
                float lw  = logf(w_s[pa] + 1e-12f) + ll;

                // logsumexp over 64 across the two warps (r10-verified path)
                float m = lw;
#pragma unroll
                for (int o = 16; o; o >>= 1)
                    m = fmaxf(m, __shfl_xor_sync(0xffffffffu, m, o));
                if (lane == 0) redm_s[warp] = m;
                asm volatile("bar.sync 1, 64;" ::: "memory");
                float mm = fmaxf(redm_s[0], redm_s[1]);
                float s  = expf(lw - mm);
#pragma unroll
                for (int o = 16; o; o >>= 1)
                    s += __shfl_xor_sync(0xffffffffu, s, o);
                if (lane == 0) reds_s[warp] = s;
                asm volatile("bar.sync 1, 64;" ::: "memory");
                float lse = logf(reds_s[0] + reds_s[1]) + mm;

                float wn = expf(lw - lse);
                float q  = ALPHA_F * wn + UNIFW;
                nv_s[pa]   = nvv;
                wn_s[pa]   = wn;
                q_s[pa]    = q;
                rinv_s[pa] = 1.0f / q;
            }
            mbar_arrive(a_rinv);        // per-lane release -> 64 arrivals

            if (warp == 0) {
                // ---- stores of step t-1 (off the recurrence critical path) --
                if (t > 0) {
                    float y = spy;
#pragma unroll
                    for (int o = 16; o; o >>= 1)
                        y += __shfl_xor_sync(0xffffffffu, y, o);
                    if (lane == 0) y_out[(size_t)(t - 1) * BB + b] = y;
                    pf[((size_t)(t - 1) * (KK * BB) + (size_t)lane * BB + b) * 5 + 4] = svra;
                    pf[((size_t)(t - 1) * (KK * BB) + (size_t)(lane + 32) * BB + b) * 5 + 4] = svrb;
                }
                // ---- wait for idx(t) (all B2(t) reads done), then C(t) ------
                mbar_wait(a_idx, (uint32_t)(t & 1));
                const int ia = idx_s[lane], ib = idx_s[lane + 32];
                float vra = nv_s[ia], vrb = nv_s[ib];
                float wra = wn_s[ia] / q_s[ia];
                float wrb = wn_s[ib] / q_s[ib];
                float ssum = wra + wrb;
#pragma unroll
                for (int o = 16; o; o >>= 1)
                    ssum += __shfl_xor_sync(0xffffffffu, ssum, o);
                wra /= ssum; wrb /= ssum;
                vol_s[lane]      = vra; vol_s[lane + 32] = vrb;
                w_s[lane]        = wra; w_s[lane + 32]   = wrb;
                svra = vra; svrb = vrb;
                spy  = vra * wra + vrb * wrb;
            }
            // bar1: warp1 may not start A(t+1) (overwriting nv/wn/q/rinv and
            // reading vol/w) until warp0 finished C(t) -- which also implies
            // all B-warps finished reading step-t state (via a_idx).
            asm volatile("bar.sync 1, 64;" ::: "memory");
        }
        // final step's outputs
        if (warp == 0) {
            float y = spy;
#pragma unroll
            for (int o = 16; o; o >>= 1)
                y += __shfl_xor_sync(0xffffffffu, y, o);
            if (lane == 0) y_out[(size_t)(TT - 1) * BB + b] = y;
            pf[((size_t)(TT - 1) * (KK * BB) + (size_t)lane * BB + b) * 5 + 4] = svra;
            pf[((size_t)(TT - 1) * (KK * BB) + (size_t)(lane + 32) * BB + b) * 5 + 4] = svrb;
        }
    } else {
        // ================= B warps (categorical rows) =======================
        const int w2    = warp - 2;
        const int nrows = (w2 < 20) ? 3 : 2;
        const int row0  = (w2 < 20) ? w2 * 3 : 60 + (w2 - 20) * 2;

        float    e0v[3], e1v[3];
        uint32_t b0v[3], b1v[3];

        for (int t = 0; t < TT; t++) {
            // ---- B1(t): state-independent, at this warp's own pace ----------
            {
                const uint2 ck = sckey[t];
                const uint32_t bb64 = (uint32_t)(b * KK);
#pragma unroll
                for (int ii = 0; ii < 3; ii++) {
                    if (ii < nrows) {
                        const uint32_t i  = (uint32_t)(row0 + ii);
                        const uint32_t cb = i * 8192u + bb64;
                        uint2 ga = tf2x32(ck.x, ck.y, 0u, cb + (uint32_t)lane);
                        uint2 gb = tf2x32(ck.x, ck.y, 0u, cb + (uint32_t)lane + 32u);
                        b0v[ii] = ga.x ^ ga.y;
                        b1v[ii] = gb.x ^ gb.y;
                        e0v[ii] = neglog_poly(b0v[ii]);
                        e1v[ii] = neglog_poly(b1v[ii]);
                    }
                }
            }
            // ---- wait only on A (never on sibling B-warps) ------------------
            mbar_wait(a_rinv, (uint32_t)(t & 1));
            {
                const float ra = rinv_s[lane];
                const float rb = rinv_s[lane + 32];
#pragma unroll
                for (int ii = 0; ii < 3; ii++) {
                    if (ii < nrows) {
                        float t0 = e0v[ii] * ra;   // positive -> uint-monotone
                        float t1 = e1v[ii] * rb;
                        uint32_t k0 = (__float_as_uint(t0) & 0xFFFFFFC0u) | (uint32_t)lane;
                        uint32_t k1 = (__float_as_uint(t1) & 0xFFFFFFC0u) | (uint32_t)(lane + 32);
                        uint32_t km = k0 < k1 ? k0 : k1;
                        uint32_t wk = __reduce_min_sync(0xffffffffu, km);
                        int bj = (int)(wk & 63u);
                        float thr = __uint_as_float(wk & 0xFFFFFFC0u) * MARGIN;
                        bool nr = ((lane      != bj) && (t0 <= thr)) ||
                                  ((lane + 32 != bj) && (t1 <= thr));
                        if (__ballot_sync(0xffffffffu, nr)) {
                            float s0 = gumbel_exact(b0v[ii]) + logf(q_s[lane]);
                            float s1 = gumbel_exact(b1v[ii]) + logf(q_s[lane + 32]);
                            float fb; int fj;
                            if (s1 > s0) { fb = s1; fj = lane + 32; }
                            else         { fb = s0; fj = lane; }
#pragma unroll
                            for (int o = 16; o; o >>= 1) {
                                float ov = __shfl_xor_sync(0xffffffffu, fb, o);
                                int   oj = __shfl_xor_sync(0xffffffffu, fj, o);
                                if (ov > fb || (ov == fb && oj < fj)) { fb = ov; fj = oj; }
                            }
                            bj = fj;
                        }
                        if (lane == 0) idx_s[row0 + ii] = bj;
                    }
                }
            }
            mbar_arrive(a_idx);   // per-lane release -> 704 arrivals; flow on
        }
    }
}

// ---------------------------------------------------------------------------
extern "C" void kernel_launch(void* const* d_in, const int* in_sizes, int n_in,
                              void* d_out, int out_size) {
    const float* obs    = (const float*)d_in[0];  // (128, 2048, 2)
    const float* vol0   = (const float*)d_in[1];  // (8192, 1)
    const float* params = (const float*)d_in[2];  // (4,)
    float* out = (float*)d_out;

    float* pf = out + (size_t)TT * BB;
    fill_const_kernel<<<65536, 256>>>(params, pf);
    garch_pf_kernel<<<BB, NTHREADS>>>(obs, vol0, params, out);
}

// round 15
// speedup vs baseline: 1.1677x; 1.1166x over previous
#include <cuda_runtime.h>
#include <stdint.h>

// Problem constants
#define TT 2048
#define BB 128
#define KK 64
#define NTHREADS 768   // 24 warps: 0-1 = A/C; 2-21 = 3 rows; 22-23 = 2 rows

// ---------------------------------------------------------------------------
// mbarrier helpers (shared-memory, cta scope)
// ---------------------------------------------------------------------------
__device__ __forceinline__ void mbar_init(uint32_t addr, uint32_t count) {
    asm volatile("mbarrier.init.shared.b64 [%0], %1;"
                 :: "r"(addr), "r"(count) : "memory");
}
__device__ __forceinline__ void mbar_arrive(uint32_t addr) {
    asm volatile("mbarrier.arrive.release.cta.shared::cta.b64 _, [%0];"
                 :: "r"(addr) : "memory");
}
__device__ __forceinline__ void mbar_wait(uint32_t addr, uint32_t parity) {
    asm volatile(
        "{\n\t"
        ".reg .pred P;\n"
        "WL_%=:\n\t"
        "mbarrier.try_wait.parity.acquire.cta.shared::cta.b64 P, [%0], %1, 0x989680;\n\t"
        "@P bra.uni WD_%=;\n\t"
        "bra.uni WL_%=;\n"
        "WD_%=:\n\t"
        "}"
        :: "r"(addr), "r"(parity) : "memory");
}

// ---------------------------------------------------------------------------
// Threefry-2x32, 20 rounds, exactly as jax._src.prng.threefry2x32 (SHF rotate)
// ---------------------------------------------------------------------------
__device__ __forceinline__ uint2 tf2x32(uint32_t k0, uint32_t k1,
                                        uint32_t x0, uint32_t x1) {
    uint32_t ks2 = k0 ^ k1 ^ 0x1BD11BDAu;
    x0 += k0; x1 += k1;
#define TFR(r) { x0 += x1; x1 = __funnelshift_l(x1, x1, (r)); x1 ^= x0; }
    TFR(13) TFR(15) TFR(26) TFR(6)
    x0 += k1; x1 += ks2 + 1u;
    TFR(17) TFR(29) TFR(16) TFR(24)
    x0 += ks2; x1 += k0 + 2u;
    TFR(13) TFR(15) TFR(26) TFR(6)
    x0 += k0; x1 += k1 + 3u;
    TFR(17) TFR(29) TFR(16) TFR(24)
    x0 += k1; x1 += ks2 + 4u;
    TFR(13) TFR(15) TFR(26) TFR(6)
    x0 += ks2; x1 += k0 + 5u;
#undef TFR
    return make_uint2(x0, x1);
}

__device__ __forceinline__ float bits_to_u01(uint32_t bits) {
    return __uint_as_float((bits >> 9) | 0x3f800000u) - 1.0f;
}

#define TINYF 1.17549435082228751e-38f

// FAST: e2 = -log2(u) via MUFU.LG2 (rt 8/SMSP per WARP -- cheap; my earlier
// "MUFU trap" costing was per-lane, off by 32x). Error: <= ~4e-7 absolute near
// u~1, <= ~4e-7 relative elsewhere. Only feeds the fast argmin key; the hybrid
// abs+rel margin below routes every possibly-affected row to the exact path.
__device__ __forceinline__ float neglog2_mufu(uint32_t bits) {
    float u = fmaxf(bits_to_u01(bits), TINYF);
    float l;
    asm("lg2.approx.f32 %0, %1;" : "=f"(l) : "f"(u));
    return -l;
}

// XLA/CHLO ErfInv32 polynomial (Giles) -- precise path (feeds state)
__device__ __forceinline__ float erfinv_xla(float x) {
    float w = -log1pf(-x * x);
    float p;
    if (w < 5.0f) {
        w = w - 2.5f;
        p = 2.81022636e-08f;
        p = fmaf(p, w, 3.43273939e-07f);
        p = fmaf(p, w, -3.5233877e-06f);
        p = fmaf(p, w, -4.39150654e-06f);
        p = fmaf(p, w, 0.00021858087f);
        p = fmaf(p, w, -0.00125372503f);
        p = fmaf(p, w, -0.00417768164f);
        p = fmaf(p, w, 0.246640727f);
        p = fmaf(p, w, 1.50140941f);
    } else {
        w = sqrtf(w) - 3.0f;
        p = -0.000200214257f;
        p = fmaf(p, w, 0.000100950558f);
        p = fmaf(p, w, 0.00134934322f);
        p = fmaf(p, w, -0.00367342844f);
        p = fmaf(p, w, 0.00573950773f);
        p = fmaf(p, w, -0.0076224613f);
        p = fmaf(p, w, 0.00943887047f);
        p = fmaf(p, w, 1.00167406f);
        p = fmaf(p, w, 2.83297682f);
    }
    return p * x;
}

// Exact reference gumbel (libdevice logf), used only on fallback rows.
__device__ __forceinline__ float gumbel_exact(uint32_t bits) {
    float u = bits_to_u01(bits);
    float v = fmaxf(u, TINYF);
    return -logf(-logf(v));
}

// ---------------------------------------------------------------------------
// Fill the 4 constant columns of pf_out once
// ---------------------------------------------------------------------------
__global__ void fill_const_kernel(const float* __restrict__ params,
                                  float* __restrict__ pf) {
    const float p0 = params[0], p1 = params[1], p2 = params[2], p3 = params[3];
    const size_t n = (size_t)TT * KK * BB;
    size_t idx = (size_t)blockIdx.x * blockDim.x + threadIdx.x;
    if (idx < n) {
        float* o = pf + idx * 5;
        o[0] = p0; o[1] = p1; o[2] = p2; o[3] = p3;
    }
}

// ---------------------------------------------------------------------------
// Persistent kernel: 1 CTA per batch element b. r14 structure (mbarriers),
// fast categorical key t = (-log2(u)) * (ln2/q) via MUFU; hybrid margin
// (rel 3e-4 + abs 3e-4) routes near-ties to the exact reference formula.
// ---------------------------------------------------------------------------
__global__ void __launch_bounds__(NTHREADS, 1)
garch_pf_kernel(const float* __restrict__ obs,     // (B, T, 2)
                const float* __restrict__ vol0,    // (K*B, 1)
                const float* __restrict__ params,  // (4,)
                float* __restrict__ out) {
    const int b    = blockIdx.x;
    const int tid  = threadIdx.x;
    const int lane = tid & 31;
    const int warp = tid >> 5;

    __shared__ uint2 skey[TT];     // per-step key_t
    __shared__ uint2 sckey[TT];    // fold_in(key_t, 1)
    __shared__ float r_s[TT];      // obs[b, t, 0]
    __shared__ float rinv_s[KK];   // ln2 / q   (fast-key scale)
    __shared__ float q_s[KK];      // q (fallback + phase C)
    __shared__ float nv_s[KK], wn_s[KK];
    __shared__ float vol_s[KK], w_s[KK];
    __shared__ int   idx_s[KK];
    __shared__ float redm_s[2], reds_s[2];
    __shared__ alignas(8) uint64_t mb_rinv, mb_idx;

    const uint32_t a_rinv = (uint32_t)__cvta_generic_to_shared(&mb_rinv);
    const uint32_t a_idx  = (uint32_t)__cvta_generic_to_shared(&mb_idx);

    if (tid == 0) {
        mbar_init(a_rinv, 64);    // all lanes of warps 0-1 arrive
        mbar_init(a_idx, 704);    // all lanes of 22 B-warps arrive
    }
    for (int t = tid; t < TT; t += NTHREADS) {
        uint2 kt = tf2x32(0u, 42u, 0u, (uint32_t)t);
        skey[t]  = kt;
        sckey[t] = tf2x32(kt.x, kt.y, 0u, 1u);
        r_s[t]   = obs[((size_t)b * TT + t) * 2];
    }
    if (warp < 2) {
        const int pa = warp * 32 + lane;
        vol_s[pa] = vol0[pa * BB + b];
        w_s[pa]   = 1.0f / 64.0f;
    }
    const float c0 = params[0], q1 = params[1], q2 = params[2], r1 = params[3];
    const float r1e = 0.001f * r1;
    __syncthreads();

    float* __restrict__ y_out = out;                    // (T, B, 1)
    float* __restrict__ pf    = out + (size_t)TT * BB;  // (T, K*B, 5)

    const float MINVAL_N = -0.99999994039535522f;
    const float SQRT2    = 1.41421356237309515f;
    const float LOG2PI   = 1.83787706640934534f;
    const float ALPHA_F  = 0.3f;
    const float UNIFW    = (float)((1.0 - 0.3) / 64.0);
    const float LN2F     = 0.69314718055994531f;
    // Hybrid fallback margin: relative covers both sides' relative rounding;
    // absolute covers MUFU's ~4e-7 abs lg2 error scaled by rinv<=91.4*ln2
    // (~2.6e-5) with ~10x headroom. Fallback rate ~3e-4/row.
    const float MARGIN_REL = 1.0003f;
    const float MARGIN_ABS = 3e-4f;

    if (warp < 2) {
        // ================= A/C warps ========================================
        const int pa = warp * 32 + lane;
        float svra = 0.f, svrb = 0.f, spy = 0.f;   // step t-1 outputs (w0)

        for (int t = 0; t < TT; t++) {
            // ---- Phase A(t): produce rinv/q/nv/wn ---------------------------
            {
                const uint2 kt = skey[t];
                const float r    = r_s[t];
                const float rr   = r * r;
                const float q2rr = (q2 * r) * r;

                uint2 bl = tf2x32(kt.x, kt.y, 0u, (uint32_t)(pa * BB + b));
                float u  = bits_to_u01(bl.x ^ bl.y);
                float v  = fmaxf(MINVAL_N, u * 2.0f + MINVAL_N);
                float eps = SQRT2 * erfinv_xla(v);
                float x   = ((c0 + q1 * vol_s[pa]) + q2rr) + r1e * eps;
                float nvv = fabsf(x) + 1e-8f;
                float ll  = -0.5f * ((rr / nvv + logf(nvv)) + LOG2PI);
                float lw  = logf(w_s[pa] + 1e-12f) + ll;

                // logsumexp over 64 across the two warps
                float m = lw;
#pragma unroll
                for (int o = 16; o; o >>= 1)
                    m = fmaxf(m, __shfl_xor_sync(0xffffffffu, m, o));
                if (lane == 0) redm_s[warp] = m;
                asm volatile("bar.sync 1, 64;" ::: "memory");
                float mm = fmaxf(redm_s[0], redm_s[1]);
                float s  = expf(lw - mm);
#pragma unroll
                for (int o = 16; o; o >>= 1)
                    s += __shfl_xor_sync(0xffffffffu, s, o);
                if (lane == 0) reds_s[warp] = s;
                asm volatile("bar.sync 1, 64;" ::: "memory");
                float lse = logf(reds_s[0] + reds_s[1]) + mm;

                float wn = expf(lw - lse);
                float q  = ALPHA_F * wn + UNIFW;
                nv_s[pa]   = nvv;
                wn_s[pa]   = wn;
                q_s[pa]    = q;
                rinv_s[pa] = LN2F / q;     // fold ln2 into the key scale
            }
            mbar_arrive(a_rinv);        // per-lane release -> 64 arrivals

            if (warp == 0) {
                // ---- stores of step t-1 (off the recurrence critical path) --
                if (t > 0) {
                    float y = spy;
#pragma unroll
                    for (int o = 16; o; o >>= 1)
                        y += __shfl_xor_sync(0xffffffffu, y, o);
                    if (lane == 0) y_out[(size_t)(t - 1) * BB + b] = y;
                    pf[((size_t)(t - 1) * (KK * BB) + (size_t)lane * BB + b) * 5 + 4] = svra;
                    pf[((size_t)(t - 1) * (KK * BB) + (size_t)(lane + 32) * BB + b) * 5 + 4] = svrb;
                }
                // ---- wait for idx(t) (all B2(t) reads done), then C(t) ------
                mbar_wait(a_idx, (uint32_t)(t & 1));
                const int ia = idx_s[lane], ib = idx_s[lane + 32];
                float vra = nv_s[ia], vrb = nv_s[ib];
                float wra = wn_s[ia] / q_s[ia];
                float wrb = wn_s[ib] / q_s[ib];
                float ssum = wra + wrb;
#pragma unroll
                for (int o = 16; o; o >>= 1)
                    ssum += __shfl_xor_sync(0xffffffffu, ssum, o);
                wra /= ssum; wrb /= ssum;
                vol_s[lane]      = vra; vol_s[lane + 32] = vrb;
                w_s[lane]        = wra; w_s[lane + 32]   = wrb;
                svra = vra; svrb = vrb;
                spy  = vra * wra + vrb * wrb;
            }
            // bar1: warp1 may not start A(t+1) until warp0 finished C(t)
            asm volatile("bar.sync 1, 64;" ::: "memory");
        }
        // final step's outputs
        if (warp == 0) {
            float y = spy;
#pragma unroll
            for (int o = 16; o; o >>= 1)
                y += __shfl_xor_sync(0xffffffffu, y, o);
            if (lane == 0) y_out[(size_t)(TT - 1) * BB + b] = y;
            pf[((size_t)(TT - 1) * (KK * BB) + (size_t)lane * BB + b) * 5 + 4] = svra;
            pf[((size_t)(TT - 1) * (KK * BB) + (size_t)(lane + 32) * BB + b) * 5 + 4] = svrb;
        }
    } else {
        // ================= B warps (categorical rows) =======================
        const int w2    = warp - 2;
        const int nrows = (w2 < 20) ? 3 : 2;
        const int row0  = (w2 < 20) ? w2 * 3 : 60 + (w2 - 20) * 2;

        float    e0v[3], e1v[3];     // -log2(u) (MUFU)
        uint32_t b0v[3], b1v[3];     // raw bits (fallback recompute)

        for (int t = 0; t < TT; t++) {
            // ---- B1(t): state-independent, at this warp's own pace ----------
            {
                const uint2 ck = sckey[t];
                const uint32_t bb64 = (uint32_t)(b * KK);
#pragma unroll
                for (int ii = 0; ii < 3; ii++) {
                    if (ii < nrows) {
                        const uint32_t i  = (uint32_t)(row0 + ii);
                        const uint32_t cb = i * 8192u + bb64;
                        uint2 ga = tf2x32(ck.x, ck.y, 0u, cb + (uint32_t)lane);
                        uint2 gb = tf2x32(ck.x, ck.y, 0u, cb + (uint32_t)lane + 32u);
                        b0v[ii] = ga.x ^ ga.y;
                        b1v[ii] = gb.x ^ gb.y;
                        e0v[ii] = neglog2_mufu(b0v[ii]);
                        e1v[ii] = neglog2_mufu(b1v[ii]);
                    }
                }
            }
            // ---- wait only on A (never on sibling B-warps) ------------------
            mbar_wait(a_rinv, (uint32_t)(t & 1));
            {
                const float ra = rinv_s[lane];
                const float rb = rinv_s[lane + 32];
#pragma unroll
                for (int ii = 0; ii < 3; ii++) {
                    if (ii < nrows) {
                        float t0 = e0v[ii] * ra;   // positive -> uint-monotone
                        float t1 = e1v[ii] * rb;
                        uint32_t k0 = (__float_as_uint(t0) & 0xFFFFFFC0u) | (uint32_t)lane;
                        uint32_t k1 = (__float_as_uint(t1) & 0xFFFFFFC0u) | (uint32_t)(lane + 32);
                        uint32_t km = k0 < k1 ? k0 : k1;
                        uint32_t wk = __reduce_min_sync(0xffffffffu, km);
                        int bj = (int)(wk & 63u);
                        float bw = __uint_as_float(wk & 0xFFFFFFC0u);
                        float thr = fmaf(bw, MARGIN_REL, MARGIN_ABS);
                        bool nr = ((lane      != bj) && (t0 <= thr)) ||
                                  ((lane + 32 != bj) && (t1 <= thr));
                        if (__ballot_sync(0xffffffffu, nr)) {
                            // exact reference formula: argmax(gumbel + log q)
                            float s0 = gumbel_exact(b0v[ii]) + logf(q_s[lane]);
                            float s1 = gumbel_exact(b1v[ii]) + logf(q_s[lane + 32]);
                            float fb; int fj;
                            if (s1 > s0) { fb = s1; fj = lane + 32; }
                            else         { fb = s0; fj = lane; }
#pragma unroll
                            for (int o = 16; o; o >>= 1) {
                                float ov = __shfl_xor_sync(0xffffffffu, fb, o);
                                int   oj = __shfl_xor_sync(0xffffffffu, fj, o);
                                if (ov > fb || (ov == fb && oj < fj)) { fb = ov; fj = oj; }
                            }
                            bj = fj;
                        }
                        if (lane == 0) idx_s[row0 + ii] = bj;
                    }
                }
            }
            mbar_arrive(a_idx);   // per-lane release -> 704 arrivals; flow on
        }
    }
}

// ---------------------------------------------------------------------------
extern "C" void kernel_launch(void* const* d_in, const int* in_sizes, int n_in,
                              void* d_out, int out_size) {
    const float* obs    = (const float*)d_in[0];  // (128, 2048, 2)
    const float* vol0   = (const float*)d_in[1];  // (8192, 1)
    const float* params = (const float*)d_in[2];  // (4,)
    float* out = (float*)d_out;

    float* pf = out + (size_t)TT * BB;
    fill_const_kernel<<<65536, 256>>>(params, pf);
    garch_pf_kernel<<<BB, NTHREADS>>>(obs, vol0, params, out);
}